// round 10
// baseline (speedup 1.0000x reference)
#include <cuda_runtime.h>
#include <math.h>

#define SEQ   256
#define BATCH 64
#define XD    64
#define FEATD 256
#define DECD  256
#define HD    512
#define KTOT  (FEATD + HD)   // 768
#define NG    128
#define NF    8
#define NB    (NG + NF)      // 136 blocks
#define NT    512            // threads per block

// ---------------- persistent device scratch ---------------------------------
__device__ float g_feat_tf[SEQ * BATCH * FEATD];
__device__ float g_act[2][BATCH * KTOT];     // [feat(256) | h(512)]
__device__ float g_dec2[2][BATCH * DECD];
__device__ int c_dec[SEQ];  __device__ volatile int f_dec[SEQ];
__device__ int c_feat[SEQ]; __device__ volatile int f_feat[SEQ];
__device__ int c_h[SEQ];    __device__ volatile int f_h[SEQ];
__device__ int c_prol;      __device__ volatile int f_prol;

__device__ __forceinline__ float sig_(float x) { return 1.0f / (1.0f + expf(-x)); }

__device__ __forceinline__ void ffma2(unsigned long long& acc,
                                      unsigned long long a, unsigned long long b) {
    asm("fma.rn.f32x2 %0, %1, %2, %0;" : "+l"(acc) : "l"(a), "l"(b));
}
__device__ __forceinline__ float pairsum(unsigned long long v) {
    float lo, hi;
    asm("mov.b64 {%0,%1}, %2;" : "=f"(lo), "=f"(hi) : "l"(v));
    return lo + hi;
}

__device__ __forceinline__ void blk_arrive(int* ct, volatile int* fl, int n) {
    __syncthreads();
    if (threadIdx.x == 0) {
        __threadfence();
        if (atomicAdd(ct, 1) == n - 1) *fl = 1;
    }
}
__device__ __forceinline__ void blk_wait(volatile int* fl) {
    if (threadIdx.x == 0) {
        while (*fl == 0) __nanosleep(20);
    }
    __syncthreads();
}

__global__ void k_reset() {
    int i = threadIdx.x;
    for (int j = i; j < SEQ; j += 256) {
        c_dec[j] = 0;  f_dec[j] = 0;
        c_feat[j] = 0; f_feat[j] = 0;
        c_h[j] = 0;    f_h[j] = 0;
    }
    if (i == 0) { c_prol = 0; f_prol = 0; }
}

// smem float offsets
// G: w_s[12288] | wdec[1024] | gex2[2048] | hs0[16640] | hs1[16640] -> 48640
// F: wout_s[16640] | wfx_s[17408] | y_s[512]                        -> 34560
// XS (prologue): 48640..48768
#define WS_OFF   0
#define WDEC_OFF 12288
#define GEX_OFF  13312
#define HS0_OFF  15360
#define HS1_OFF  32000
#define WOUT_OFF 0
#define WFX_OFF  16640
#define YS_OFF   34048
#define XS_OFF   48640
#define SM_FLOATS 48768
#define HSP 260   // padded row stride

__global__ void __launch_bounds__(NT, 1)
k_persist(const float* __restrict__ x,   const float* __restrict__ ms,
          const float* __restrict__ Wfx, const float* __restrict__ bfx,
          const float* __restrict__ Wih, const float* __restrict__ Whh,
          const float* __restrict__ bih, const float* __restrict__ bhh,
          const float* __restrict__ Whx, const float* __restrict__ bhx,
          const float* __restrict__ Wout,const float* __restrict__ bout,
          float* __restrict__ out) {
    extern __shared__ float smem[];
    const int blk = blockIdx.x;
    const int tid = threadIdx.x;
    const int wid = tid >> 5;
    const int l   = tid & 31;

    // ===================== prologue: feat_tf (all blocks, 2 rows/iter) =======
    {
        const int col = tid & 255;
        const int rs  = tid >> 8;              // row select 0/1
        float wreg[XD];
        const float4* wf4 = (const float4*)(Wfx + col * XD);
#pragma unroll
        for (int i = 0; i < XD / 4; i++) ((float4*)wreg)[i] = __ldg(wf4 + i);
        float biasf = __ldg(&bfx[col]);
        float* xs = smem + XS_OFF;             // 2 rows x 64
        for (int r0 = blk * 2; r0 < SEQ * BATCH; r0 += NB * 2) {
            __syncthreads();
            if (tid < 32 && (r0 + (tid >> 4)) < SEQ * BATCH)
                ((float4*)xs)[tid] = __ldg((const float4*)(x + r0 * XD) + tid);
            __syncthreads();
            int row = r0 + rs;
            if (row < SEQ * BATCH) {
                const float* xr = xs + rs * XD;
                float s = biasf;
#pragma unroll
                for (int k = 0; k < XD; k++) s += xr[k] * wreg[k];
                g_feat_tf[row * FEATD + col] = tanhf(s);
            }
        }
        __syncthreads();
    }

    if (blk < NG) {
        // ========================== G block =================================
        float* w_s  = smem + WS_OFF;
        float* wdec = smem + WDEC_OFF;
        float* gex2 = smem + GEX_OFF;          // [2][64][16]
        float* hs0  = smem + HS0_OFF;
        float* hs1  = smem + HS1_OFF;
        const int n0 = blk * 4;

        for (int idx = tid; idx < KTOT * 16; idx += NT) {
            int k  = idx >> 4;
            int lc = idx & 15;
            int gi = lc >> 2;
            int u  = lc & 3;
            int j  = gi * HD + n0 + u;
            float v = (k < FEATD) ? Wih[j * FEATD + k] : Whh[j * HD + (k - FEATD)];
            w_s[(k >> 1) * 32 + lc * 2 + (k & 1)] = v;
        }
        for (int idx = tid; idx < 2 * HD; idx += NT)
            wdec[idx] = Whx[2 * blk * HD + idx];

        const int half = tid >> 8;             // K-half 0/1
        const int b    = (tid >> 2) & 63;
        const int cg   = tid & 3;
        const int jb   = cg * HD + n0;
        const float bb0 = __ldg(&bih[jb + 0]) + __ldg(&bhh[jb + 0]);
        const float bb1 = __ldg(&bih[jb + 1]) + __ldg(&bhh[jb + 1]);
        const float bb2 = __ldg(&bih[jb + 2]) + __ldg(&bhh[jb + 2]);
        const float bb3 = __ldg(&bih[jb + 3]) + __ldg(&bhh[jb + 3]);
        const float bhx0 = __ldg(&bhx[2 * blk]);
        const float bhx1 = __ldg(&bhx[2 * blk + 1]);
        float c_reg = 0.0f;
        __stcg(&g_act[0][b * KTOT + FEATD + n0 + cg], 0.0f);  // h(0)=0 (dup write ok)

        blk_arrive(&c_prol, &f_prol, NB);
        blk_wait(&f_prol);

        const int i0 = half * 32;              // ulonglong2 index range for my half

        for (int t = 0; t < SEQ; t++) {
            const int p = t & 1;
            if (t > 0) blk_wait(&f_h[t - 1]);

            // ---- stage h chunk0 (k 256..511) -------------------------------
            {
                const float* src = g_act[p] + FEATD;
#pragma unroll
                for (int it = 0; it < 8; it++) {
                    int idx = it * NT + tid;
                    int row = idx >> 6, col = idx & 63;
                    float4 v = __ldcg((const float4*)(src + row * KTOT) + col);
                    *(float4*)(hs0 + row * HSP + col * 4) = v;
                }
            }
            __syncthreads();
            // ---- stage h chunk1 (k 512..767) (overlaps chunk0 compute) -----
            {
                const float* src = g_act[p] + FEATD + 256;
#pragma unroll
                for (int it = 0; it < 8; it++) {
                    int idx = it * NT + tid;
                    int row = idx >> 6, col = idx & 63;
                    float4 v = __ldcg((const float4*)(src + row * KTOT) + col);
                    *(float4*)(hs1 + row * HSP + col * 4) = v;
                }
            }

            unsigned long long acc0 = 0ull, acc1 = 0ull, acc2 = 0ull, acc3 = 0ull;
            float sd[4][2];
#pragma unroll
            for (int r = 0; r < 4; r++) { sd[r][0] = 0.f; sd[r][1] = 0.f; }

            // ---- gates on chunk0 (my K-half) -------------------------------
            {
                const ulonglong2* hv = (const ulonglong2*)(hs0 + b * HSP);
#pragma unroll 8
                for (int i = i0; i < i0 + 32; i++) {
                    ulonglong2 av = hv[i];
                    int kp = 128 + 2 * i;
                    ulonglong2 a  = *(const ulonglong2*)&w_s[kp * 32 + cg * 8];
                    ulonglong2 bq = *(const ulonglong2*)&w_s[kp * 32 + cg * 8 + 4];
                    ulonglong2 cq = *(const ulonglong2*)&w_s[(kp + 1) * 32 + cg * 8];
                    ulonglong2 dq = *(const ulonglong2*)&w_s[(kp + 1) * 32 + cg * 8 + 4];
                    ffma2(acc0, av.x, a.x);  ffma2(acc1, av.x, a.y);
                    ffma2(acc2, av.x, bq.x); ffma2(acc3, av.x, bq.y);
                    ffma2(acc0, av.y, cq.x); ffma2(acc1, av.y, cq.y);
                    ffma2(acc2, av.y, dq.x); ffma2(acc3, av.y, dq.y);
                }
            }
            // ---- dec partial chunk0 (16 warps x 4 batches) -----------------
            {
#pragma unroll
                for (int r = 0; r < 4; r++) {
                    int bb = wid * 4 + r;
                    const float4* hv4 = (const float4*)(hs0 + bb * HSP);
                    float4 h0 = hv4[l], h1 = hv4[l + 32];
#pragma unroll
                    for (int ci = 0; ci < 2; ci++) {
                        const float4* wv = (const float4*)(wdec + ci * HD);
                        float4 w0 = wv[l], w1 = wv[l + 32];
                        sd[r][ci] += h0.x*w0.x + h0.y*w0.y + h0.z*w0.z + h0.w*w0.w
                                   + h1.x*w1.x + h1.y*w1.y + h1.z*w1.z + h1.w*w1.w;
                    }
                }
            }
            __syncthreads();   // hs1 ready
            // ---- gates on chunk1 -------------------------------------------
            {
                const ulonglong2* hv = (const ulonglong2*)(hs1 + b * HSP);
#pragma unroll 8
                for (int i = i0; i < i0 + 32; i++) {
                    ulonglong2 av = hv[i];
                    int kp = 256 + 2 * i;
                    ulonglong2 a  = *(const ulonglong2*)&w_s[kp * 32 + cg * 8];
                    ulonglong2 bq = *(const ulonglong2*)&w_s[kp * 32 + cg * 8 + 4];
                    ulonglong2 cq = *(const ulonglong2*)&w_s[(kp + 1) * 32 + cg * 8];
                    ulonglong2 dq = *(const ulonglong2*)&w_s[(kp + 1) * 32 + cg * 8 + 4];
                    ffma2(acc0, av.x, a.x);  ffma2(acc1, av.x, a.y);
                    ffma2(acc2, av.x, bq.x); ffma2(acc3, av.x, bq.y);
                    ffma2(acc0, av.y, cq.x); ffma2(acc1, av.y, cq.y);
                    ffma2(acc2, av.y, dq.x); ffma2(acc3, av.y, dq.y);
                }
            }
            // ---- dec partial chunk1 + finalize -----------------------------
            {
#pragma unroll
                for (int r = 0; r < 4; r++) {
                    int bb = wid * 4 + r;
                    const float4* hv4 = (const float4*)(hs1 + bb * HSP);
                    float4 h0 = hv4[l], h1 = hv4[l + 32];
#pragma unroll
                    for (int ci = 0; ci < 2; ci++) {
                        const float4* wv = (const float4*)(wdec + ci * HD + 256);
                        float4 w0 = wv[l], w1 = wv[l + 32];
                        sd[r][ci] += h0.x*w0.x + h0.y*w0.y + h0.z*w0.z + h0.w*w0.w
                                   + h1.x*w1.x + h1.y*w1.y + h1.z*w1.z + h1.w*w1.w;
                    }
                }
#pragma unroll
                for (int r = 0; r < 4; r++) {
#pragma unroll
                    for (int ci = 0; ci < 2; ci++) {
                        float s = sd[r][ci];
                        s += __shfl_xor_sync(0xffffffffu, s, 16);
                        s += __shfl_xor_sync(0xffffffffu, s, 8);
                        s += __shfl_xor_sync(0xffffffffu, s, 4);
                        s += __shfl_xor_sync(0xffffffffu, s, 2);
                        s += __shfl_xor_sync(0xffffffffu, s, 1);
                        if (l == 0) {
                            int bb = wid * 4 + r;
                            float bias = ci ? bhx1 : bhx0;
                            __stcg(&g_dec2[p][bb * DECD + 2 * blk + ci], tanhf(s + bias));
                        }
                    }
                }
            }
            blk_arrive(&c_dec[t], &f_dec[t], NG);
            blk_wait(&f_feat[t]);

            // ---- stage feat + gates feat part ------------------------------
            {
                const float* src = g_act[p];
#pragma unroll
                for (int it = 0; it < 8; it++) {
                    int idx = it * NT + tid;
                    int row = idx >> 6, col = idx & 63;
                    float4 v = __ldcg((const float4*)(src + row * KTOT) + col);
                    *(float4*)(hs0 + row * HSP + col * 4) = v;
                }
            }
            __syncthreads();
            {
                const ulonglong2* hv = (const ulonglong2*)(hs0 + b * HSP);
#pragma unroll 8
                for (int i = i0; i < i0 + 32; i++) {
                    ulonglong2 av = hv[i];
                    int kp = 2 * i;
                    ulonglong2 a  = *(const ulonglong2*)&w_s[kp * 32 + cg * 8];
                    ulonglong2 bq = *(const ulonglong2*)&w_s[kp * 32 + cg * 8 + 4];
                    ulonglong2 cq = *(const ulonglong2*)&w_s[(kp + 1) * 32 + cg * 8];
                    ulonglong2 dq = *(const ulonglong2*)&w_s[(kp + 1) * 32 + cg * 8 + 4];
                    ffma2(acc0, av.x, a.x);  ffma2(acc1, av.x, a.y);
                    ffma2(acc2, av.x, bq.x); ffma2(acc3, av.x, bq.y);
                    ffma2(acc0, av.y, cq.x); ffma2(acc1, av.y, cq.y);
                    ffma2(acc2, av.y, dq.x); ffma2(acc3, av.y, dq.y);
                }
            }
            // half0 folds biases into its partial
            {
                float v0 = pairsum(acc0), v1 = pairsum(acc1);
                float v2 = pairsum(acc2), v3 = pairsum(acc3);
                if (half == 0) { v0 += bb0; v1 += bb1; v2 += bb2; v3 += bb3; }
                float* gx = gex2 + half * 1024 + b * 16 + cg * 4;
                gx[0] = v0; gx[1] = v1; gx[2] = v2; gx[3] = v3;
            }
            __syncthreads();
            if (tid < 256) {
                int u = cg;
                float i_v = gex2[b * 16 + 0  + u] + gex2[1024 + b * 16 + 0  + u];
                float f_v = gex2[b * 16 + 4  + u] + gex2[1024 + b * 16 + 4  + u];
                float gg  = gex2[b * 16 + 8  + u] + gex2[1024 + b * 16 + 8  + u];
                float o_v = gex2[b * 16 + 12 + u] + gex2[1024 + b * 16 + 12 + u];
                float c_new = sig_(f_v) * c_reg + sig_(i_v) * tanhf(gg);
                float h_new = sig_(o_v) * tanhf(c_new);
                c_reg = c_new;
                __stcg(&g_act[p ^ 1][b * KTOT + FEATD + n0 + u], h_new);
            }
            blk_arrive(&c_h[t], &f_h[t], NG);
        }
    } else {
        // ========================== F block =================================
        const int f = blk - NG;
        float* wout_s = smem + WOUT_OFF;
        float* wfx_s  = smem + WFX_OFF;
        float* y_s    = smem + YS_OFF;
        for (int idx = tid; idx < 64 * DECD; idx += NT) {
            int r = idx >> 8, cx = idx & 255;
            wout_s[r * 260 + cx] = Wout[idx];
        }
        for (int idx = tid; idx < FEATD * XD; idx += NT) {
            int r = idx >> 6, cx = idx & 63;
            wfx_s[r * 68 + cx] = Wfx[idx];
        }
        const int bgy = f * 8 + wid;           // y-warp batch (wid<8)
        const int w2  = wid >> 1;              // feat pair id 0..7
        const int sel = wid & 1;
        const int bgf = f * 8 + w2;            // feat batch
        const float bo0 = __ldg(&bout[l]);
        const float bo1 = __ldg(&bout[l + 32]);

        blk_arrive(&c_prol, &f_prol, NB);
        blk_wait(&f_prol);

        // feat(0) = feat_tf[0]
        {
#pragma unroll
            for (int j = 0; j < 4; j++) {
                int c = l + 32 * (sel * 4 + j);
                __stcg(&g_act[0][bgf * KTOT + c],
                       __ldg(&g_feat_tf[bgf * FEATD + c]));
            }
        }
        blk_arrive(&c_feat[0], &f_feat[0], NF);

        for (int t = 0; t < SEQ; t++) {
            const int p = t & 1;
            blk_wait(&f_dec[t]);
            if (wid < 8) {
                const float4* dv = (const float4*)(g_dec2[p] + bgy * DECD);
                const float4* w0v = (const float4*)(wout_s + l * 260);
                const float4* w1v = (const float4*)(wout_s + (l + 32) * 260);
                float s0 = 0.f, s1 = 0.f;
#pragma unroll 8
                for (int k4 = 0; k4 < DECD / 4; k4++) {
                    float4 d = __ldcg(dv + k4);
                    float4 a = w0v[k4], bq = w1v[k4];
                    s0 += d.x*a.x + d.y*a.y + d.z*a.z + d.w*a.w;
                    s1 += d.x*bq.x + d.y*bq.y + d.z*bq.z + d.w*bq.w;
                }
                float y0 = s0 + bo0, y1 = s1 + bo1;
                out[(t * BATCH + bgy) * XD + l]      = y0;
                out[(t * BATCH + bgy) * XD + l + 32] = y1;
                y_s[wid * 64 + l]      = y0;
                y_s[wid * 64 + l + 32] = y1;
            }
            __syncthreads();   // y_s visible to feat warp pairs
            if (t + 1 < SEQ) {
                float m1 = __ldg(&ms[t + 1]);
                const float* yrow = y_s + w2 * 64;
#pragma unroll
                for (int j = 0; j < 4; j++) {
                    int c = l + 32 * (sel * 4 + j);
                    const float4* wv = (const float4*)(wfx_s + c * 68);
                    float s = __ldg(&bfx[c]);
#pragma unroll
                    for (int k4 = 0; k4 < XD / 4; k4++) {
                        float4 yv = *(const float4*)(yrow + 4 * k4);
                        float4 wf = wv[k4];
                        s += yv.x*wf.x + yv.y*wf.y + yv.z*wf.z + yv.w*wf.w;
                    }
                    float ftf = __ldg(&g_feat_tf[((t + 1) * BATCH + bgf) * FEATD + c]);
                    float v = m1 * tanhf(s) + (1.0f - m1) * ftf;
                    __stcg(&g_act[(t + 1) & 1][bgf * KTOT + c], v);
                }
                blk_arrive(&c_feat[t + 1], &f_feat[t + 1], NF);
            }
        }
    }
}

// ---------------------------------------------------------------------------
extern "C" void kernel_launch(void* const* d_in, const int* in_sizes, int n_in,
                              void* d_out, int out_size) {
    const float* x    = (const float*)d_in[0];
    const float* ms   = (const float*)d_in[1];
    const float* Wfx  = (const float*)d_in[2];
    const float* bfx  = (const float*)d_in[3];
    const float* Wih  = (const float*)d_in[4];
    const float* Whh  = (const float*)d_in[5];
    const float* bih  = (const float*)d_in[6];
    const float* bhh  = (const float*)d_in[7];
    const float* Whx  = (const float*)d_in[8];
    const float* bhx  = (const float*)d_in[9];
    const float* Wout = (const float*)d_in[10];
    const float* bout = (const float*)d_in[11];
    float* out = (float*)d_out;

    const int smem_p = SM_FLOATS * sizeof(float);   // 195072 B
    static bool attr_set = false;
    if (!attr_set) {
        cudaFuncSetAttribute(k_persist, cudaFuncAttributeMaxDynamicSharedMemorySize, smem_p);
        attr_set = true;
    }

    k_reset<<<1, 256>>>();
    k_persist<<<NB, NT, smem_p>>>(x, ms, Wfx, bfx, Wih, Whh, bih, bhh,
                                  Whx, bhx, Wout, bout, out);
}